// round 13
// baseline (speedup 1.0000x reference)
#include <cuda_runtime.h>
#include <cuda_fp16.h>
#include <math.h>
#include <stdint.h>

// Problem constants
#define B_    32
#define N_    256
#define E_    1024
#define T_    5
#define ANNO_ 18
#define AACT_ 3
#define BN_   8192

// Scales: fp16 operands stored x2^8 each (products 2^16);
// fp8 sections [A_lo*2^12 | A_hi] x [W_hi*2^4 | W_lo*2^16] (products 2^16).
#define SCALE_OUT (1.0f / 65536.0f)

// ---------------- scratch (static device globals; no allocation) -------------
__device__ __align__(256) float g_h  [BN_ * E_];
__device__ __align__(256) float g_gi [BN_ * 3 * E_];
__device__ __align__(256) float g_gh [BN_ * 3 * E_];
__device__ __align__(256) float g_gid[BN_ * 6 * E_];
__device__ __align__(256) float g_mid[BN_ * E_];
__device__ __align__(256) float g_out3[BN_ * AACT_];
__device__ float g_vn[B_ * 64];
__device__ float g_va[B_ * 64];
__device__ float g_maxv[B_];

// fp16 hi operands (stored x2^8) + fp8 correction operands
__device__ __align__(256) __half  g_Wih16 [3072 * 2048];
__device__ __align__(256) uint8_t g_Wih8  [3072 * 4096];
__device__ __align__(256) __half  g_Whh16 [3072 * 1024];
__device__ __align__(256) uint8_t g_Whh8  [3072 * 2048];
__device__ __align__(256) __half  g_dWih16[6144 * 1216];
__device__ __align__(256) uint8_t g_dWih8 [6144 * 2432];
__device__ __align__(256) __half  g_W116  [1024 * 2048];
__device__ __align__(256) uint8_t g_W18   [1024 * 4096];
__device__ __align__(256) __half  g_adjO  [B_ * 256 * 512];   // [A|A] x2^8
__device__ __align__(256) __half  g_adjI  [B_ * 256 * 512];
__device__ __align__(256) __half  g_ap16  [BN_ * 2048];       // a_hi x2^8
__device__ __align__(256) uint8_t g_ap8   [BN_ * 4096];       // [a_lo*2^12 | a_hi]
__device__ __align__(256) __half  g_hp16  [BN_ * 1024];
__device__ __align__(256) uint8_t g_h8    [BN_ * 2048];
__device__ __align__(256) __half  g_ht    [B_ * 1024 * 512];  // h^T [hi|lo] x2^8
__device__ __align__(256) __half  g_cp16  [BN_ * 1216];
__device__ __align__(256) uint8_t g_c8    [BN_ * 2432];
__device__ __align__(256) __half  g_hid16 [BN_ * 2048];
__device__ __align__(256) uint8_t g_hid8  [BN_ * 4096];

// ---------------- helpers -----------------------------------------------------
__device__ __forceinline__ uint32_t s2u(const void* p) {
    uint32_t a;
    asm("{ .reg .u64 t; cvta.to.shared.u64 t, %1; cvt.u32.u64 %0, t; }" : "=r"(a) : "l"(p));
    return a;
}
__device__ __forceinline__ uint64_t g2u(const void* p) {
    uint64_t a;
    asm("cvta.to.global.u64 %0, %1;" : "=l"(a) : "l"(p));
    return a;
}
// pack two floats to e4m3x2: x0 -> low byte, x1 -> high byte
__device__ __forceinline__ uint16_t pk8(float x0, float x1) {
    uint16_t r;
    asm("cvt.rn.satfinite.e4m3x2.f32 %0, %1, %2;" : "=h"(r) : "f"(x1), "f"(x0));
    return r;
}

#define CP_ASYNC16(smem_u32, gptr64) \
    asm volatile("cp.async.cg.shared.global [%0], [%1], 16;" :: "r"(smem_u32), "l"(gptr64))
#define CP_COMMIT() asm volatile("cp.async.commit_group;" ::: "memory")
#define CP_WAIT(n)  asm volatile("cp.async.wait_group %0;" :: "n"(n) : "memory")

#define LDSM4(r0, r1, r2, r3, addr)                                           \
    asm volatile("ldmatrix.sync.aligned.m8n8.x4.shared.b16 {%0,%1,%2,%3}, [%4];" \
                 : "=r"(r0), "=r"(r1), "=r"(r2), "=r"(r3) : "r"(addr))

#define MMA16(d, a, b)                                                        \
    asm volatile(                                                             \
        "mma.sync.aligned.m16n8k16.row.col.f32.f16.f16.f32 "                  \
        "{%0,%1,%2,%3}, {%4,%5,%6,%7}, {%8,%9}, {%0,%1,%2,%3};"               \
        : "+f"((d)[0]), "+f"((d)[1]), "+f"((d)[2]), "+f"((d)[3])              \
        : "r"((a)[0]), "r"((a)[1]), "r"((a)[2]), "r"((a)[3]),                 \
          "r"((b)[0]), "r"((b)[1]))

#define MMA8(d, a, b)                                                         \
    asm volatile(                                                             \
        "mma.sync.aligned.m16n8k32.row.col.f32.e4m3.e4m3.f32 "                \
        "{%0,%1,%2,%3}, {%4,%5,%6,%7}, {%8,%9}, {%0,%1,%2,%3};"               \
        : "+f"((d)[0]), "+f"((d)[1]), "+f"((d)[2]), "+f"((d)[3])              \
        : "r"((a)[0]), "r"((a)[1]), "r"((a)[2]), "r"((a)[3]),                 \
          "r"((b)[0]), "r"((b)[1]))

// ---------------- unified mixed fp16/fp8 GEMM ---------------------------------
// C = (A16*B16^T [K16 fp16 iters] + A8*B8^T [K8 fp8 iters]) * 2^-16
// CTA 128x128, 128B stage rows, 8 warps (64x32), 3-stage cp.async, 2 CTA/SM.
// spl mode (adjacency): writes a_hi16 (x2^8, pitch 2048) + a8 (pitch 4096)
// at GLOBAL row z*256 + local row (bugfix vs round 12).
#define STAGE_BYTES 32768
#define B_OFF       16384
#define SMEM_TOTAL_GEMM (3 * STAGE_BYTES)

__global__ __launch_bounds__(256, 2)
void gemm_mma(const __half* __restrict__ A16, const __half* __restrict__ B16,
              const uint8_t* __restrict__ A8, const uint8_t* __restrict__ B8,
              int K16, int K8, long long sA16, long long sB16,
              float* __restrict__ C, int ldc, const float* __restrict__ bias, int relu,
              __half* __restrict__ splH, uint8_t* __restrict__ spl8, int colOff)
{
    extern __shared__ char smem[];
    const uint32_t smb = s2u(smem);

    const int tid  = threadIdx.x;
    const int wid  = tid >> 5, lane = tid & 31;
    const int g    = lane >> 2, tig = lane & 3;
    const int wm0  = (wid & 1) * 64;
    const int wn0  = (wid >> 1) * 32;
    const int z    = blockIdx.z;

    const int n16 = K16 >> 6;
    const int n8  = K8 >> 7;
    const int nIter = n16 + n8;

    // ---- cp.async source bases ----
    const int rbase = tid >> 3;            // 0..31
    const int ch    = tid & 7;
    const uint64_t bA16 = g2u((const char*)(A16 + (long long)z * sA16
                              + (long long)(blockIdx.y * 128) * K16) + ch * 16);
    const uint64_t bB16 = g2u((const char*)(B16 + (long long)z * sB16
                              + (long long)(blockIdx.x * 128) * K16) + ch * 16);
    const uint64_t bA8  = A8 ? g2u(A8 + (long long)(blockIdx.y * 128) * K8 + ch * 16) : 0;
    const uint64_t bB8  = B8 ? g2u(B8 + (long long)(blockIdx.x * 128) * K8 + ch * 16) : 0;

    uint32_t ro16[4], ro8[4], sAo[4], sBo[4];
#pragma unroll
    for (int i = 0; i < 4; i++) {
        const int r = rbase + 32 * i;
        ro16[i] = (uint32_t)r * (uint32_t)(K16 * 2);
        ro8[i]  = (uint32_t)r * (uint32_t)K8;
        const uint32_t sw = (uint32_t)((ch ^ (r & 7)) << 4);
        sAo[i] = smb + r * 128 + sw;
        sBo[i] = smb + B_OFF + r * 128 + sw;
    }

#define LOAD_STAGE(s, idx)                                                    \
    do {                                                                      \
        const uint32_t so = (uint32_t)(s) * STAGE_BYTES;                      \
        if ((idx) < n16) {                                                    \
            const long long kB = (long long)(idx) * 128;                      \
            _Pragma("unroll")                                                 \
            for (int i_ = 0; i_ < 4; i_++) {                                  \
                CP_ASYNC16(sAo[i_] + so, bA16 + ro16[i_] + kB);               \
                CP_ASYNC16(sBo[i_] + so, bB16 + ro16[i_] + kB);               \
            }                                                                 \
        } else {                                                              \
            const long long kB = (long long)((idx) - n16) * 128;              \
            _Pragma("unroll")                                                 \
            for (int i_ = 0; i_ < 4; i_++) {                                  \
                CP_ASYNC16(sAo[i_] + so, bA8 + ro8[i_] + kB);                 \
                CP_ASYNC16(sBo[i_] + so, bB8 + ro8[i_] + kB);                 \
            }                                                                 \
        }                                                                     \
    } while (0)

    // ---- ldmatrix per-lane constants ----
    const int xorL = lane & 7;
    const int cA   = lane >> 4;
    const int cB   = (lane >> 3) & 1;
    uint32_t aoff[4], boff[2];
#pragma unroll
    for (int i = 0; i < 4; i++)
        aoff[i] = (uint32_t)(wm0 + i * 16 + (lane & 15)) * 128;
#pragma unroll
    for (int jp = 0; jp < 2; jp++)
        boff[jp] = (uint32_t)(wn0 + jp * 16 + (lane & 7) + ((lane & 16) >> 1)) * 128 + B_OFF;

    float acc[4][4][4];
#pragma unroll
    for (int i = 0; i < 4; i++)
#pragma unroll
        for (int j = 0; j < 4; j++)
#pragma unroll
            for (int c = 0; c < 4; c++) acc[i][j][c] = 0.f;

    LOAD_STAGE(0, 0); CP_COMMIT();
    if (nIter > 1) LOAD_STAGE(1, 1);
    CP_COMMIT();

    int stage = 0;
    for (int it = 0; it < nIter; ++it) {
        CP_WAIT(1);
        __syncthreads();

        if (it + 2 < nIter) {
            int ns = stage + 2; if (ns >= 3) ns -= 3;
            LOAD_STAGE(ns, it + 2);
        }
        CP_COMMIT();

        const uint32_t sAs = smb + stage * STAGE_BYTES;
        if (it < n16) {
#pragma unroll
            for (int ks = 0; ks < 4; ks++) {
                const int c2 = ks * 2;
                uint32_t af[4][4], bf[4][2];
#pragma unroll
                for (int i = 0; i < 4; i++) {
                    const uint32_t ad = sAs + aoff[i] + (uint32_t)(((c2 + cA) ^ xorL) << 4);
                    LDSM4(af[i][0], af[i][1], af[i][2], af[i][3], ad);
                }
#pragma unroll
                for (int jp = 0; jp < 2; jp++) {
                    const uint32_t bd = sAs + boff[jp] + (uint32_t)(((c2 + cB) ^ xorL) << 4);
                    LDSM4(bf[2 * jp][0], bf[2 * jp][1], bf[2 * jp + 1][0], bf[2 * jp + 1][1], bd);
                }
#pragma unroll
                for (int i = 0; i < 4; i++)
#pragma unroll
                    for (int j = 0; j < 4; j++)
                        MMA16(acc[i][j], af[i], bf[j]);
            }
        } else {
#pragma unroll
            for (int ks = 0; ks < 4; ks++) {
                const int c2 = ks * 2;
                uint32_t af[4][4], bf[4][2];
#pragma unroll
                for (int i = 0; i < 4; i++) {
                    const uint32_t ad = sAs + aoff[i] + (uint32_t)(((c2 + cA) ^ xorL) << 4);
                    LDSM4(af[i][0], af[i][1], af[i][2], af[i][3], ad);
                }
#pragma unroll
                for (int jp = 0; jp < 2; jp++) {
                    const uint32_t bd = sAs + boff[jp] + (uint32_t)(((c2 + cB) ^ xorL) << 4);
                    LDSM4(bf[2 * jp][0], bf[2 * jp][1], bf[2 * jp + 1][0], bf[2 * jp + 1][1], bd);
                }
#pragma unroll
                for (int i = 0; i < 4; i++)
#pragma unroll
                    for (int j = 0; j < 4; j++)
                        MMA8(acc[i][j], af[i], bf[j]);
            }
        }
        if (++stage == 3) stage = 0;
    }

    // ---- epilogue ----
    const int rowBase = blockIdx.y * 128 + wm0 + g;
    const int colBase = blockIdx.x * 128 + wn0 + tig * 2;
    if (splH) {
        const long long zRow = (long long)z * 256;   // BUGFIX: batch row offset
#pragma unroll
        for (int i = 0; i < 4; i++)
#pragma unroll
            for (int rr = 0; rr < 2; rr++) {
                const long long row = zRow + rowBase + i * 16 + rr * 8;
                __half*  hp = splH + row * 2048 + colOff;
                uint8_t* p8 = spl8 + row * 4096 + colOff;
#pragma unroll
                for (int j = 0; j < 4; j++) {
                    const int col = colBase + j * 8;
                    float v0 = acc[i][j][rr * 2] * SCALE_OUT;
                    float v1 = acc[i][j][rr * 2 + 1] * SCALE_OUT;
                    __half h0s = __float2half_rn(v0 * 256.f);
                    __half h1s = __float2half_rn(v1 * 256.f);
                    float hf0 = __half2float(h0s) * (1.f / 256.f);
                    float hf1 = __half2float(h1s) * (1.f / 256.f);
                    __half2 ph; ph.x = h0s; ph.y = h1s;
                    *(__half2*)(hp + col) = ph;
                    *(uint16_t*)(p8 + col)        = pk8((v0 - hf0) * 4096.f, (v1 - hf1) * 4096.f);
                    *(uint16_t*)(p8 + 2048 + col) = pk8(hf0, hf1);
                }
            }
    } else {
        float* Cb = C;
#pragma unroll
        for (int i = 0; i < 4; i++)
#pragma unroll
            for (int rr = 0; rr < 2; rr++) {
                const int row = rowBase + i * 16 + rr * 8;
                float* rp = Cb + (long long)row * ldc;
#pragma unroll
                for (int j = 0; j < 4; j++) {
                    const int col = colBase + j * 8;
                    float v0 = acc[i][j][rr * 2] * SCALE_OUT;
                    float v1 = acc[i][j][rr * 2 + 1] * SCALE_OUT;
                    if (bias) { v0 += bias[col]; v1 += bias[col + 1]; }
                    if (relu) { v0 = fmaxf(v0, 0.f); v1 = fmaxf(v1, 0.f); }
                    float2 v; v.x = v0; v.y = v1;
                    *(float2*)(rp + col) = v;
                }
            }
    }
#undef LOAD_STAGE
}

// ---------------- prep / fused elementwise kernels ----------------------------

// weights: dstH[r*K+c] = fp16(w)*2^8 ; dst8 = [fp8(hi*2^4) | fp8(lo*2^16)]
__global__ void k_prepW(const float* __restrict__ src, __half* __restrict__ dstH,
                        uint8_t* __restrict__ dst8, int K, int total)
{
    int i = blockIdx.x * 256 + threadIdx.x;
    if (i >= total) return;
    int r = i / K, c = i - r * K;
    float w = src[i];
    __half hs = __float2half_rn(w * 256.f);
    float hf = __half2float(hs) * (1.f / 256.f);
    float lo = w - hf;
    dstH[(long long)r * K + c] = hs;
    uint8_t* d8 = dst8 + (long long)r * 2 * K;
    d8[c]     = (uint8_t)(pk8(hf * 16.f, 0.f) & 0xFF);
    d8[K + c] = (uint8_t)(pk8(lo * 65536.f, 0.f) & 0xFF);
}

// adjacency (0/1 exact): [A|A] stored x2^8
__global__ void k_adjprep(const float* __restrict__ so, const float* __restrict__ si)
{
    int i = blockIdx.x * 256 + threadIdx.x;
    int br = i >> 8, c = i & 255;
    __half vo = __float2half_rn(so[i] * 256.f);
    __half vi = __float2half_rn(si[i] * 256.f);
    g_adjO[(long long)br * 512 + c] = vo;  g_adjO[(long long)br * 512 + 256 + c] = vo;
    g_adjI[(long long)br * 512 + c] = vi;  g_adjI[(long long)br * 512 + 256 + c] = vi;
}

// writes hi16 (x2^8) + fp8 pair [lo*2^12 | hi] for a 4-elem group
__device__ __forceinline__ void store_split4(const float* v, __half* hp, uint8_t* p8,
                                             int loOff, int hiOff)
{
    __half hs[4]; float hf[4];
#pragma unroll
    for (int c = 0; c < 4; c++) {
        hs[c] = __float2half_rn(v[c] * 256.f);
        hf[c] = __half2float(hs[c]) * (1.f / 256.f);
    }
    __half2 a; a.x = hs[0]; a.y = hs[1];
    __half2 b; b.x = hs[2]; b.y = hs[3];
    *(__half2*)(hp)     = a;
    *(__half2*)(hp + 2) = b;
    uint32_t lo01 = pk8((v[0] - hf[0]) * 4096.f, (v[1] - hf[1]) * 4096.f);
    uint32_t lo23 = pk8((v[2] - hf[2]) * 4096.f, (v[3] - hf[3]) * 4096.f);
    uint32_t hi01 = pk8(hf[0], hf[1]);
    uint32_t hi23 = pk8(hf[2], hf[3]);
    *(uint32_t*)(p8 + loOff) = lo01 | (lo23 << 16);
    *(uint32_t*)(p8 + hiOff) = hi01 | (hi23 << 16);
}

// h = annotation @ anno_W (4 cols/thread)
__global__ void k_embed(const float* __restrict__ anno, const float* __restrict__ W)
{
    int r = blockIdx.x;
    __shared__ float arow[ANNO_];
    if (threadIdx.x < ANNO_) arow[threadIdx.x] = anno[r * ANNO_ + threadIdx.x];
    __syncthreads();
    int e = threadIdx.x * 4;
    float s[4] = {0.f, 0.f, 0.f, 0.f};
#pragma unroll
    for (int k = 0; k < ANNO_; k++) {
        float a = arow[k];
        float4 wv = *(const float4*)(W + k * E_ + e);
        s[0] = fmaf(a, wv.x, s[0]); s[1] = fmaf(a, wv.y, s[1]);
        s[2] = fmaf(a, wv.z, s[2]); s[3] = fmaf(a, wv.w, s[3]);
    }
    float4 hv; hv.x = s[0]; hv.y = s[1]; hv.z = s[2]; hv.w = s[3];
    *(float4*)(g_h + (long long)r * E_ + e) = hv;
    store_split4(s, g_hp16 + (long long)r * 1024 + e,
                 g_h8 + (long long)r * 2048 + e, 0, 1024);
}

// per-batch transpose: g_ht[b][e] = [hi*2^8 | lo*2^8] over n
__global__ void k_transpose()
{
    __shared__ float t[32][33];
    int e0 = blockIdx.x * 32, n0 = blockIdx.y * 32, b = blockIdx.z;
    int tx = threadIdx.x, ty = threadIdx.y;   // 32 x 8
#pragma unroll
    for (int j = 0; j < 32; j += 8)
        t[ty + j][tx] = g_h[((long long)b * 256 + n0 + ty + j) * 1024 + e0 + tx];
    __syncthreads();
    if (tx < 16) {
#pragma unroll
        for (int j = 0; j < 32; j += 8) {
            int e = e0 + ty + j;
            float v0 = t[2 * tx][ty + j];
            float v1 = t[2 * tx + 1][ty + j];
            __half h0 = __float2half_rn(v0 * 256.f);
            __half h1 = __float2half_rn(v1 * 256.f);
            float l0 = v0 - __half2float(h0) * (1.f / 256.f);
            float l1 = v1 - __half2float(h1) * (1.f / 256.f);
            __half2 ph; ph.x = h0; ph.y = h1;
            __half2 pl; pl.x = __float2half_rn(l0 * 256.f); pl.y = __float2half_rn(l1 * 256.f);
            __half* rp = g_ht + ((long long)b * 1024 + e) * 512;
            *(__half2*)(rp + n0 + 2 * tx)       = ph;
            *(__half2*)(rp + 256 + n0 + 2 * tx) = pl;
        }
    }
}

__device__ __forceinline__ float sigmoidf_(float x) { return 1.f / (1.f + expf(-x)); }

// encoder GRU update, 4 elems/thread
__global__ void k_gru()
{
    long long idx = ((long long)blockIdx.x * 256 + threadIdx.x) * 4;  // r*1024 + e
    int r = (int)(idx >> 10);
    int e = (int)(idx & 1023);
    const float* gi = g_gi + (long long)r * 3072 + e;
    const float* gh = g_gh + (long long)r * 3072 + e;
    float4 gir = *(const float4*)gi;
    float4 giz = *(const float4*)(gi + 1024);
    float4 gin = *(const float4*)(gi + 2048);
    float4 ghr = *(const float4*)gh;
    float4 ghz = *(const float4*)(gh + 1024);
    float4 ghn = *(const float4*)(gh + 2048);
    float4 hv  = *(const float4*)(g_h + idx);
    float hn[4];
    {
        const float* pir = &gir.x; const float* piz = &giz.x; const float* pin = &gin.x;
        const float* phr = &ghr.x; const float* phz = &ghz.x; const float* phn = &ghn.x;
        const float* ph  = &hv.x;
#pragma unroll
        for (int c = 0; c < 4; c++) {
            float rr = sigmoidf_(pir[c] + phr[c]);
            float zz = sigmoidf_(piz[c] + phz[c]);
            float nn = tanhf(pin[c] + rr * phn[c]);
            hn[c] = (1.f - zz) * nn + zz * ph[c];
        }
    }
    float4 ho; ho.x = hn[0]; ho.y = hn[1]; ho.z = hn[2]; ho.w = hn[3];
    *(float4*)(g_h + idx) = ho;
    store_split4(hn, g_hp16 + (long long)r * 1024 + e,
                 g_h8 + (long long)r * 2048 + e, 0, 1024);
}

__global__ void k_vnf(const float* __restrict__ vnow, const float* __restrict__ vall,
                      const float* __restrict__ Wn, const float* __restrict__ Wa)
{
    int b = blockIdx.x, d = threadIdx.x;
    float sn = 0.f, sa = 0.f;
#pragma unroll
    for (int k = 0; k < 16; k++) {
        sn = fmaf(vnow[b * 16 + k], Wn[k * 64 + d], sn);
        sa = fmaf(vall[b * 16 + k], Wa[k * 64 + d], sa);
    }
    g_vn[b * 64 + d] = sn;
    g_va[b * 64 + d] = sa;
}

// concat -> cp16 [8192,1216] + c8 [8192,2432]
__global__ void k_concat(const int* __restrict__ from_node, const float* __restrict__ pos_enc)
{
    int r = blockIdx.x, b = r >> 8;
    __half*  dH = g_cp16 + (long long)r * 1216;
    uint8_t* d8 = g_c8 + (long long)r * 2432;
    const float* hs = g_h + (long long)r * E_;
    {
        int i = threadIdx.x * 4;
        float4 v = *(const float4*)(hs + i);
        float vv[4] = {v.x, v.y, v.z, v.w};
        store_split4(vv, dH + i, d8 + i, 0, 1216);
    }
    int fn = from_node[b];
    for (int i = threadIdx.x; i < 64; i += blockDim.x) {
        float vals[3] = {pos_enc[fn * 64 + i], g_va[b * 64 + i], g_vn[b * 64 + i]};
#pragma unroll
        for (int s = 0; s < 3; s++) {
            int cidx = 1024 + s * 64 + i;
            float v = vals[s];
            __half hsv = __float2half_rn(v * 256.f);
            float hf = __half2float(hsv) * (1.f / 256.f);
            dH[cidx] = hsv;
            d8[cidx]        = (uint8_t)(pk8((v - hf) * 4096.f, 0.f) & 0xFF);
            d8[1216 + cidx] = (uint8_t)(pk8(hf, 0.f) & 0xFF);
        }
    }
}

// decoder GRU (h0=0 => gh=bhh), 4 elems/thread
__global__ void k_decgru(const float* __restrict__ bhh, float* __restrict__ hidden_out)
{
    long long idx = ((long long)blockIdx.x * 256 + threadIdx.x) * 4;  // r*2048 + e
    int r = (int)(idx >> 11);
    int e = (int)(idx & 2047);
    const float* gi = g_gid + (long long)r * 6144 + e;
    float4 gir = *(const float4*)gi;
    float4 giz = *(const float4*)(gi + 2048);
    float4 gin = *(const float4*)(gi + 4096);
    float4 bhr = *(const float4*)(bhh + e);
    float4 bhz = *(const float4*)(bhh + 2048 + e);
    float4 bhn = *(const float4*)(bhh + 4096 + e);
    float hv[4];
    {
        const float* pir = &gir.x; const float* piz = &giz.x; const float* pin = &gin.x;
        const float* pbr = &bhr.x; const float* pbz = &bhz.x; const float* pbn = &bhn.x;
#pragma unroll
        for (int c = 0; c < 4; c++) {
            float rr = sigmoidf_(pir[c] + pbr[c]);
            float zz = sigmoidf_(piz[c] + pbz[c]);
            float nn = tanhf(pin[c] + rr * pbn[c]);
            hv[c] = (1.f - zz) * nn;
        }
    }
    float4 ho; ho.x = hv[0]; ho.y = hv[1]; ho.z = hv[2]; ho.w = hv[3];
    *(float4*)(hidden_out + idx) = ho;
    store_split4(hv, g_hid16 + (long long)r * 2048 + e,
                 g_hid8 + (long long)r * 4096 + e, 0, 2048);
}

// thin head: out3 = mid @ W2^T + b2
__global__ void k_out2(const float* __restrict__ W2, const float* __restrict__ b2)
{
    __shared__ float w[3][1024];
    int tid = threadIdx.x;
    for (int i = tid; i < 3 * 1024; i += 256) w[i >> 10][i & 1023] = W2[i];
    __syncthreads();
    int warp = tid >> 5, lane = tid & 31;
    int r = blockIdx.x * 8 + warp;
    const float* m = g_mid + (long long)r * 1024;
    float s0 = 0.f, s1 = 0.f, s2 = 0.f;
    for (int k = lane; k < 1024; k += 32) {
        float mv = m[k];
        s0 = fmaf(mv, w[0][k], s0);
        s1 = fmaf(mv, w[1][k], s1);
        s2 = fmaf(mv, w[2][k], s2);
    }
#pragma unroll
    for (int off = 16; off; off >>= 1) {
        s0 += __shfl_down_sync(0xffffffffu, s0, off);
        s1 += __shfl_down_sync(0xffffffffu, s1, off);
        s2 += __shfl_down_sync(0xffffffffu, s2, off);
    }
    if (lane == 0) {
        g_out3[r * 3 + 0] = s0 + b2[0];
        g_out3[r * 3 + 1] = s1 + b2[1];
        g_out3[r * 3 + 2] = s2 + b2[2];
    }
}

__global__ void k_max()
{
    int b = blockIdx.x;
    __shared__ float sm[256];
    float mx = -INFINITY;
    for (int i = threadIdx.x; i < N_ * AACT_; i += 256)
        mx = fmaxf(mx, g_out3[b * N_ * AACT_ + i]);
    sm[threadIdx.x] = mx;
    __syncthreads();
    for (int s = 128; s; s >>= 1) {
        if (threadIdx.x < s) sm[threadIdx.x] = fmaxf(sm[threadIdx.x], sm[threadIdx.x + s]);
        __syncthreads();
    }
    if (threadIdx.x == 0) g_maxv[b] = sm[0];
}

__global__ void k_final(const int* __restrict__ mask, float* __restrict__ out)
{
    int r = blockIdx.x * 256 + threadIdx.x;
    if (r >= BN_) return;
    int b = r >> 8;
    float mv = g_maxv[b] + 1.f;
    float mf = (mask[r] == 1) ? 1.f : 1e10f;
    out[r]                 = mf * (g_out3[r * 3 + 0] - mv) + 1.f;
    out[BN_ + r * 2 + 0]   = mf * (g_out3[r * 3 + 1] - mv) + 1.f;
    out[BN_ + r * 2 + 1]   = mf * (g_out3[r * 3 + 2] - mv) + 1.f;
}

// ---------------- launcher ----------------------------------------------------
extern "C" void kernel_launch(void* const* d_in, const int* in_sizes, int n_in,
                              void* d_out, int out_size)
{
    const float* annotation = (const float*)d_in[0];
    const float* A_out      = (const float*)d_in[1];
    const float* A_in       = (const float*)d_in[2];
    const int*   from_node  = (const int*)  d_in[3];
    const float* vnf_now    = (const float*)d_in[4];
    const float* vnf_all    = (const float*)d_in[5];
    const int*   mask       = (const int*)  d_in[6];
    const float* anno_W     = (const float*)d_in[7];
    const float* gru_Wih    = (const float*)d_in[8];
    const float* gru_Whh    = (const float*)d_in[9];
    const float* vnf_now_W  = (const float*)d_in[10];
    const float* vnf_all_W  = (const float*)d_in[11];
    const float* dgru_Wih   = (const float*)d_in[12];
    // d_in[13] = dgru_Whh: unused (h0 == 0 -> gh == dgru_bhh exactly)
    const float* dgru_bih   = (const float*)d_in[14];
    const float* dgru_bhh   = (const float*)d_in[15];
    const float* out_W1     = (const float*)d_in[16];
    const float* out_b1     = (const float*)d_in[17];
    const float* out_W2     = (const float*)d_in[18];
    const float* out_b2     = (const float*)d_in[19];
    const float* pos_enc    = (const float*)d_in[20];

    float* out = (float*)d_out;
    float* hidden = out + BN_ + BN_ * 2;

    cudaFuncSetAttribute(gemm_mma, cudaFuncAttributeMaxDynamicSharedMemorySize,
                         SMEM_TOTAL_GEMM);

    float *p_gi, *p_gh, *p_gid, *p_mid;
    __half *p_Wih16, *p_Whh16, *p_dWih16, *p_W116, *p_adjO, *p_adjI;
    __half *p_ap16, *p_hp16, *p_ht, *p_cp16, *p_hid16;
    uint8_t *p_Wih8, *p_Whh8, *p_dWih8, *p_W18, *p_ap8, *p_h8, *p_c8, *p_hid8;
    cudaGetSymbolAddress((void**)&p_gi, g_gi);
    cudaGetSymbolAddress((void**)&p_gh, g_gh);
    cudaGetSymbolAddress((void**)&p_gid, g_gid);
    cudaGetSymbolAddress((void**)&p_mid, g_mid);
    cudaGetSymbolAddress((void**)&p_Wih16, g_Wih16);
    cudaGetSymbolAddress((void**)&p_Wih8, g_Wih8);
    cudaGetSymbolAddress((void**)&p_Whh16, g_Whh16);
    cudaGetSymbolAddress((void**)&p_Whh8, g_Whh8);
    cudaGetSymbolAddress((void**)&p_dWih16, g_dWih16);
    cudaGetSymbolAddress((void**)&p_dWih8, g_dWih8);
    cudaGetSymbolAddress((void**)&p_W116, g_W116);
    cudaGetSymbolAddress((void**)&p_W18, g_W18);
    cudaGetSymbolAddress((void**)&p_adjO, g_adjO);
    cudaGetSymbolAddress((void**)&p_adjI, g_adjI);
    cudaGetSymbolAddress((void**)&p_ap16, g_ap16);
    cudaGetSymbolAddress((void**)&p_ap8, g_ap8);
    cudaGetSymbolAddress((void**)&p_hp16, g_hp16);
    cudaGetSymbolAddress((void**)&p_h8, g_h8);
    cudaGetSymbolAddress((void**)&p_ht, g_ht);
    cudaGetSymbolAddress((void**)&p_cp16, g_cp16);
    cudaGetSymbolAddress((void**)&p_c8, g_c8);
    cudaGetSymbolAddress((void**)&p_hid16, g_hid16);
    cudaGetSymbolAddress((void**)&p_hid8, g_hid8);

    // ---- prep ----
    k_prepW<<<(3072 * 2048 + 255) / 256, 256>>>(gru_Wih, p_Wih16, p_Wih8, 2048, 3072 * 2048);
    k_prepW<<<(3072 * 1024 + 255) / 256, 256>>>(gru_Whh, p_Whh16, p_Whh8, 1024, 3072 * 1024);
    k_adjprep<<<(B_ * 256 * 256) / 256, 256>>>(A_out, A_in);
    k_embed<<<BN_, 256>>>(annotation, anno_W);

    // ---- T encoder GRU steps ----
    for (int t = 0; t < T_; t++) {
        k_transpose<<<dim3(32, 8, 32), dim3(32, 8)>>>();
        // a_out/a_in = Adj @ h  (pure fp16 exact; spl epilogue -> ap16/ap8)
        gemm_mma<<<dim3(8, 2, 32), 256, SMEM_TOTAL_GEMM>>>(
            p_adjO, p_ht, nullptr, nullptr, 512, 0,
            256LL * 512, 1024LL * 512,
            nullptr, 0, nullptr, 0, p_ap16, p_ap8, 0);
        gemm_mma<<<dim3(8, 2, 32), 256, SMEM_TOTAL_GEMM>>>(
            p_adjI, p_ht, nullptr, nullptr, 512, 0,
            256LL * 512, 1024LL * 512,
            nullptr, 0, nullptr, 0, p_ap16, p_ap8, 1024);
        // gi = a @ Wih^T  [8192,3072]  K16=2048, K8=4096
        gemm_mma<<<dim3(24, 64, 1), 256, SMEM_TOTAL_GEMM>>>(
            p_ap16, p_Wih16, p_ap8, p_Wih8, 2048, 4096, 0, 0,
            p_gi, 3072, nullptr, 0, nullptr, nullptr, 0);
        // gh = h @ Whh^T  [8192,3072]  K16=1024, K8=2048
        gemm_mma<<<dim3(24, 64, 1), 256, SMEM_TOTAL_GEMM>>>(
            p_hp16, p_Whh16, p_h8, p_Whh8, 1024, 2048, 0, 0,
            p_gh, 3072, nullptr, 0, nullptr, nullptr, 0);
        k_gru<<<BN_ * E_ / 1024, 256>>>();
    }

    // ---- decoder prep + decoder ----
    k_prepW<<<(6144 * 1216 + 255) / 256, 256>>>(dgru_Wih, p_dWih16, p_dWih8, 1216, 6144 * 1216);
    k_prepW<<<(1024 * 2048 + 255) / 256, 256>>>(out_W1, p_W116, p_W18, 2048, 1024 * 2048);
    k_vnf<<<B_, 64>>>(vnf_now, vnf_all, vnf_now_W, vnf_all_W);
    k_concat<<<BN_, 256>>>(from_node, pos_enc);
    // gi_dec = concat @ dWih^T + bih  [8192,6144]  K16=1216, K8=2432
    gemm_mma<<<dim3(48, 64, 1), 256, SMEM_TOTAL_GEMM>>>(
        p_cp16, p_dWih16, p_c8, p_dWih8, 1216, 2432, 0, 0,
        p_gid, 6144, dgru_bih, 0, nullptr, nullptr, 0);
    k_decgru<<<BN_ * 2 * E_ / 1024, 256>>>(dgru_bhh, hidden);
    // mid = relu(hidden @ W1^T + b1)  [8192,1024]  K16=2048, K8=4096
    gemm_mma<<<dim3(8, 64, 1), 256, SMEM_TOTAL_GEMM>>>(
        p_hid16, p_W116, p_hid8, p_W18, 2048, 4096, 0, 0,
        p_mid, 1024, out_b1, 1, nullptr, nullptr, 0);

    // ---- head ----
    k_out2<<<BN_ / 8, 256>>>(out_W2, out_b2);
    k_max<<<B_, 256>>>();
    k_final<<<BN_ / 256, 256>>>(mask, out);
}

// round 17
// speedup vs baseline: 1.1470x; 1.1470x over previous
#include <cuda_runtime.h>
#include <cuda_fp16.h>
#include <math.h>
#include <stdint.h>

// Problem constants
#define B_    32
#define N_    256
#define E_    1024
#define T_    5
#define ANNO_ 18
#define AACT_ 3
#define BN_   8192

// ---------------- scratch (static device globals; no allocation) -------------
__device__ __align__(256) float g_h  [BN_ * E_];
__device__ __align__(256) float g_gi [BN_ * 3 * E_];
__device__ __align__(256) float g_gh [BN_ * 3 * E_];
__device__ __align__(256) float g_gid[BN_ * 6 * E_];
__device__ __align__(256) float g_mid[BN_ * E_];
__device__ __align__(256) float g_out3[BN_ * AACT_];
__device__ float g_vn[B_ * 64];
__device__ float g_va[B_ * 64];
__device__ float g_maxv[B_];

// fp16 3-term split operands (merged-K layouts)
// weights: [hi|hi|lo]   activations: [hi|lo|hi]
// => A_hi*W_hi + A_lo*W_hi + A_hi*W_lo  (residual ~2^-22)
__device__ __align__(256) __half g_Wihp [3072 * 6144];
__device__ __align__(256) __half g_Whhp [3072 * 3072];
__device__ __align__(256) __half g_dWihp[6144 * 3648];
__device__ __align__(256) __half g_W1p  [1024 * 6144];
__device__ __align__(256) __half g_adjO [B_ * 256 * 512];
__device__ __align__(256) __half g_adjI [B_ * 256 * 512];
__device__ __align__(256) __half g_ap   [BN_ * 6144];
__device__ __align__(256) __half g_hp   [BN_ * 3072];
__device__ __align__(256) __half g_ht   [B_ * 1024 * 512];
__device__ __align__(256) __half g_cp   [BN_ * 3648];
__device__ __align__(256) __half g_hidp [BN_ * 6144];

// ---------------- helpers -----------------------------------------------------
__device__ __forceinline__ uint32_t s2u(const void* p) {
    uint32_t a;
    asm("{ .reg .u64 t; cvta.to.shared.u64 t, %1; cvt.u32.u64 %0, t; }" : "=r"(a) : "l"(p));
    return a;
}
__device__ __forceinline__ uint64_t g2u(const void* p) {
    uint64_t a;
    asm("cvta.to.global.u64 %0, %1;" : "=l"(a) : "l"(p));
    return a;
}

#define CP_ASYNC16(smem_u32, gptr64) \
    asm volatile("cp.async.cg.shared.global [%0], [%1], 16;" :: "r"(smem_u32), "l"(gptr64))
#define CP_COMMIT() asm volatile("cp.async.commit_group;" ::: "memory")
#define CP_WAIT(n)  asm volatile("cp.async.wait_group %0;" :: "n"(n) : "memory")

#define LDSM4(r0, r1, r2, r3, addr)                                           \
    asm volatile("ldmatrix.sync.aligned.m8n8.x4.shared.b16 {%0,%1,%2,%3}, [%4];" \
                 : "=r"(r0), "=r"(r1), "=r"(r2), "=r"(r3) : "r"(addr))

#define MMA16816(d, a, b)                                                     \
    asm volatile(                                                             \
        "mma.sync.aligned.m16n8k16.row.col.f32.f16.f16.f32 "                  \
        "{%0,%1,%2,%3}, {%4,%5,%6,%7}, {%8,%9}, {%0,%1,%2,%3};"               \
        : "+f"((d)[0]), "+f"((d)[1]), "+f"((d)[2]), "+f"((d)[3])              \
        : "r"((a)[0]), "r"((a)[1]), "r"((a)[2]), "r"((a)[3]),                 \
          "r"((b)[0]), "r"((b)[1]))

// ---------------- persistent mma.sync GEMM ------------------------------------
// C[M,N] = A[M,K'] * B[N,K']^T, fp16 K-major. CTA tile 128x128, BK=64,
// 8 warps (64x32), XOR-swizzled SMEM + ldmatrix.x4, 3-stage cp.async,
// 96KB smem, 2 CTA/SM. PERSISTENT: grid = 2*SMs; each CTA strides over the
// tiles of up to TWO jobs (removes wave quantization; balances mixed-K jobs).
#define STAGE_BYTES 32768
#define B_OFF       16384
#define SMEM_TOTAL_GEMM (3 * STAGE_BYTES)

struct GJob {
    const __half* A; const __half* B;
    int Kp; long long sA; long long sB;   // batch strides (elements)
    float* C; int ldc;
    const float* bias; int relu;
    __half* spl; int splPitch; int splK; int colOff;  // 3-way split epilogue
    int gx, gy, nt;  // tiles per row/col; nt = gx*gy*batches
};

__global__ __launch_bounds__(256, 2)
void gemm_mma(GJob j0, GJob j1, int ntTotal)
{
    extern __shared__ char smem[];
    const uint32_t smb = s2u(smem);

    const int tid  = threadIdx.x;
    const int wid  = tid >> 5, lane = tid & 31;
    const int g    = lane >> 2, tig = lane & 3;
    const int wm0  = (wid & 1) * 64;
    const int wn0  = (wid >> 1) * 32;

    // tile-invariant lane constants
    const int rbase = tid >> 3;            // 0..31  (cp.async row group)
    const int ch    = tid & 7;             // 16B chunk within 128B row
    uint32_t sAo[4], sBo[4];
#pragma unroll
    for (int i = 0; i < 4; i++) {
        const int r = rbase + 32 * i;
        const uint32_t sw = (uint32_t)((ch ^ (r & 7)) << 4);
        sAo[i] = smb + r * 128 + sw;
        sBo[i] = smb + B_OFF + r * 128 + sw;
    }
    const int xorL = lane & 7;
    const int cA   = lane >> 4;
    const int cB   = (lane >> 3) & 1;
    uint32_t aoff[4], boff[2];
#pragma unroll
    for (int i = 0; i < 4; i++)
        aoff[i] = (uint32_t)(wm0 + i * 16 + (lane & 15)) * 128;
#pragma unroll
    for (int jp = 0; jp < 2; jp++)
        boff[jp] = (uint32_t)(wn0 + jp * 16 + (lane & 7) + ((lane & 16) >> 1)) * 128 + B_OFF;

    for (int t = blockIdx.x; t < ntTotal; t += gridDim.x) {
        GJob J = j0;
        int tt = t;
        if (tt >= j0.nt) { J = j1; tt -= j0.nt; }
        const int per = J.gx * J.gy;
        const int z  = tt / per;
        const int r2 = tt - z * per;
        const int by = r2 / J.gx;
        const int bx = r2 - by * J.gx;

        __syncthreads();   // protect smem stage reuse across tiles

        const __half* Ab = J.A + (long long)z * J.sA + (long long)(by * 128) * J.Kp;
        const __half* Bb = J.B + (long long)z * J.sB + (long long)(bx * 128) * J.Kp;
        uint64_t gA[4], gB[4];
#pragma unroll
        for (int i = 0; i < 4; i++) {
            const int r = rbase + 32 * i;
            gA[i] = g2u((const char*)Ab + (long long)r * (J.Kp * 2) + ch * 16);
            gB[i] = g2u((const char*)Bb + (long long)r * (J.Kp * 2) + ch * 16);
        }

#define LOAD_STAGE(s, idx)                                                 \
        do {                                                               \
            const long long kB = (long long)(idx) * 128;                   \
            const uint32_t so = (uint32_t)(s) * STAGE_BYTES;               \
            CP_ASYNC16(sAo[0] + so, gA[0] + kB);                           \
            CP_ASYNC16(sAo[1] + so, gA[1] + kB);                           \
            CP_ASYNC16(sAo[2] + so, gA[2] + kB);                           \
            CP_ASYNC16(sAo[3] + so, gA[3] + kB);                           \
            CP_ASYNC16(sBo[0] + so, gB[0] + kB);                           \
            CP_ASYNC16(sBo[1] + so, gB[1] + kB);                           \
            CP_ASYNC16(sBo[2] + so, gB[2] + kB);                           \
            CP_ASYNC16(sBo[3] + so, gB[3] + kB);                           \
        } while (0)

        float acc[4][4][4];
#pragma unroll
        for (int i = 0; i < 4; i++)
#pragma unroll
            for (int j = 0; j < 4; j++)
#pragma unroll
                for (int c = 0; c < 4; c++) acc[i][j][c] = 0.f;

        const int nIter = J.Kp >> 6;

        LOAD_STAGE(0, 0); CP_COMMIT();
        if (nIter > 1) LOAD_STAGE(1, 1);
        CP_COMMIT();

        int stage = 0;
        for (int it = 0; it < nIter; ++it) {
            CP_WAIT(1);
            __syncthreads();

            if (it + 2 < nIter) {
                int ns = stage + 2; if (ns >= 3) ns -= 3;
                LOAD_STAGE(ns, it + 2);
            }
            CP_COMMIT();

            const uint32_t sAs = smb + stage * STAGE_BYTES;
#pragma unroll
            for (int ks = 0; ks < 4; ks++) {
                const int c2 = ks * 2;
                uint32_t af[4][4], bf[4][2];
#pragma unroll
                for (int i = 0; i < 4; i++) {
                    const uint32_t ad = sAs + aoff[i] + (uint32_t)(((c2 + cA) ^ xorL) << 4);
                    LDSM4(af[i][0], af[i][1], af[i][2], af[i][3], ad);
                }
#pragma unroll
                for (int jp = 0; jp < 2; jp++) {
                    const uint32_t bd = sAs + boff[jp] + (uint32_t)(((c2 + cB) ^ xorL) << 4);
                    LDSM4(bf[2 * jp][0], bf[2 * jp][1], bf[2 * jp + 1][0], bf[2 * jp + 1][1], bd);
                }
#pragma unroll
                for (int i = 0; i < 4; i++)
#pragma unroll
                    for (int j = 0; j < 4; j++)
                        MMA16816(acc[i][j], af[i], bf[j]);
            }
            if (++stage == 3) stage = 0;
        }

        // ---- epilogue ----
        const int rowBase = by * 128 + wm0 + g;
        const int colBase = bx * 128 + wn0 + tig * 2;
        if (J.spl) {
            const long long zRow = (long long)z * (J.gy * 128);
#pragma unroll
            for (int i = 0; i < 4; i++)
#pragma unroll
                for (int rr = 0; rr < 2; rr++) {
                    const long long row = zRow + rowBase + i * 16 + rr * 8;
                    __half* rp = J.spl + row * J.splPitch + J.colOff;
#pragma unroll
                    for (int j = 0; j < 4; j++) {
                        const int col = colBase + j * 8;
                        float v0 = acc[i][j][rr * 2], v1 = acc[i][j][rr * 2 + 1];
                        __half h0 = __float2half_rn(v0), h1 = __float2half_rn(v1);
                        __half l0 = __float2half_rn(v0 - __half2float(h0));
                        __half l1 = __float2half_rn(v1 - __half2float(h1));
                        __half2 ph; ph.x = h0; ph.y = h1;
                        __half2 pl; pl.x = l0; pl.y = l1;
                        *(__half2*)(rp + col)              = ph;
                        *(__half2*)(rp + J.splK + col)     = pl;
                        *(__half2*)(rp + 2 * J.splK + col) = ph;
                    }
                }
        } else {
#pragma unroll
            for (int i = 0; i < 4; i++)
#pragma unroll
                for (int rr = 0; rr < 2; rr++) {
                    const int row = rowBase + i * 16 + rr * 8;
                    float* rp = J.C + (long long)row * J.ldc;
#pragma unroll
                    for (int j = 0; j < 4; j++) {
                        const int col = colBase + j * 8;
                        float v0 = acc[i][j][rr * 2], v1 = acc[i][j][rr * 2 + 1];
                        if (J.bias) { v0 += J.bias[col]; v1 += J.bias[col + 1]; }
                        if (J.relu) { v0 = fmaxf(v0, 0.f); v1 = fmaxf(v1, 0.f); }
                        float2 v; v.x = v0; v.y = v1;
                        *(float2*)(rp + col) = v;
                    }
                }
        }
#undef LOAD_STAGE
    }
}

// ---------------- prep / fused elementwise kernels ----------------------------

__device__ __forceinline__ void split2(float v, __half& hi, __half& lo) {
    hi = __float2half_rn(v);
    lo = __float2half_rn(v - __half2float(hi));
}
__device__ __forceinline__ __half2 mkh2(__half a, __half b) {
    __half2 r; r.x = a; r.y = b; return r;
}

// weights: dst[R,3K] = [hi | hi | lo]
__global__ void k_prepW(const float* __restrict__ src, __half* __restrict__ dst,
                        int K, int total)
{
    int i = blockIdx.x * 256 + threadIdx.x;
    if (i >= total) return;
    int r = i / K, c = i - r * K;
    __half hi, lo; split2(src[i], hi, lo);
    __half* d = dst + (long long)r * 3 * K;
    d[c] = hi; d[K + c] = hi; d[2 * K + c] = lo;
}

// adjacency (0/1 exact): dst[b][r][c] = dst[b][r][256+c] = fp16(src)
__global__ void k_adjprep(const float* __restrict__ so, const float* __restrict__ si)
{
    int i = blockIdx.x * 256 + threadIdx.x;
    int br = i >> 8, c = i & 255;
    __half vo = __float2half_rn(so[i]);
    __half vi = __float2half_rn(si[i]);
    g_adjO[(long long)br * 512 + c] = vo;  g_adjO[(long long)br * 512 + 256 + c] = vo;
    g_adjI[(long long)br * 512 + c] = vi;  g_adjI[(long long)br * 512 + 256 + c] = vi;
}

// h = annotation @ anno_W (4 cols/thread); split g_hp [hi|lo|hi]
__global__ void k_embed(const float* __restrict__ anno, const float* __restrict__ W)
{
    int r = blockIdx.x;
    __shared__ float arow[ANNO_];
    if (threadIdx.x < ANNO_) arow[threadIdx.x] = anno[r * ANNO_ + threadIdx.x];
    __syncthreads();
    int e = threadIdx.x * 4;
    float s[4] = {0.f, 0.f, 0.f, 0.f};
#pragma unroll
    for (int k = 0; k < ANNO_; k++) {
        float a = arow[k];
        float4 wv = *(const float4*)(W + k * E_ + e);
        s[0] = fmaf(a, wv.x, s[0]); s[1] = fmaf(a, wv.y, s[1]);
        s[2] = fmaf(a, wv.z, s[2]); s[3] = fmaf(a, wv.w, s[3]);
    }
    float4 hv; hv.x = s[0]; hv.y = s[1]; hv.z = s[2]; hv.w = s[3];
    *(float4*)(g_h + (long long)r * E_ + e) = hv;
    __half hi[4], lo[4];
#pragma unroll
    for (int c = 0; c < 4; c++) split2(s[c], hi[c], lo[c]);
    __half* hp = g_hp + (long long)r * 3072 + e;
    *(__half2*)(hp)        = mkh2(hi[0], hi[1]); *(__half2*)(hp + 2)      = mkh2(hi[2], hi[3]);
    *(__half2*)(hp + 1024) = mkh2(lo[0], lo[1]); *(__half2*)(hp + 1026)   = mkh2(lo[2], lo[3]);
    *(__half2*)(hp + 2048) = mkh2(hi[0], hi[1]); *(__half2*)(hp + 2050)   = mkh2(hi[2], hi[3]);
}

// per-batch transpose-split: g_ht[b][e][n]=hi(h[b][n][e]), [e][256+n]=lo
__global__ void k_transpose()
{
    __shared__ float t[32][33];
    int e0 = blockIdx.x * 32, n0 = blockIdx.y * 32, b = blockIdx.z;
    int tx = threadIdx.x, ty = threadIdx.y;   // 32 x 8
#pragma unroll
    for (int j = 0; j < 32; j += 8)
        t[ty + j][tx] = g_h[((long long)b * 256 + n0 + ty + j) * 1024 + e0 + tx];
    __syncthreads();
    if (tx < 16) {
#pragma unroll
        for (int j = 0; j < 32; j += 8) {
            int e = e0 + ty + j;
            float v0 = t[2 * tx][ty + j];
            float v1 = t[2 * tx + 1][ty + j];
            __half h0, l0, h1, l1;
            split2(v0, h0, l0); split2(v1, h1, l1);
            __half* rp = g_ht + ((long long)b * 1024 + e) * 512;
            *(__half2*)(rp + n0 + 2 * tx)       = mkh2(h0, h1);
            *(__half2*)(rp + 256 + n0 + 2 * tx) = mkh2(l0, l1);
        }
    }
}

__device__ __forceinline__ float sigmoidf_(float x) { return 1.f / (1.f + expf(-x)); }

// encoder GRU update, 4 elems/thread: g_h (f32, in place) + g_hp split
__global__ void k_gru()
{
    long long idx = ((long long)blockIdx.x * 256 + threadIdx.x) * 4;  // r*1024 + e
    int r = (int)(idx >> 10);
    int e = (int)(idx & 1023);
    const float* gi = g_gi + (long long)r * 3072 + e;
    const float* gh = g_gh + (long long)r * 3072 + e;
    float4 gir = *(const float4*)gi;
    float4 giz = *(const float4*)(gi + 1024);
    float4 gin = *(const float4*)(gi + 2048);
    float4 ghr = *(const float4*)gh;
    float4 ghz = *(const float4*)(gh + 1024);
    float4 ghn = *(const float4*)(gh + 2048);
    float4 hv  = *(const float4*)(g_h + idx);
    float hn[4];
    {
        const float* pir = &gir.x; const float* piz = &giz.x; const float* pin = &gin.x;
        const float* phr = &ghr.x; const float* phz = &ghz.x; const float* phn = &ghn.x;
        const float* ph  = &hv.x;
#pragma unroll
        for (int c = 0; c < 4; c++) {
            float rr = sigmoidf_(pir[c] + phr[c]);
            float zz = sigmoidf_(piz[c] + phz[c]);
            float nn = tanhf(pin[c] + rr * phn[c]);
            hn[c] = (1.f - zz) * nn + zz * ph[c];
        }
    }
    float4 ho; ho.x = hn[0]; ho.y = hn[1]; ho.z = hn[2]; ho.w = hn[3];
    *(float4*)(g_h + idx) = ho;
    __half hi[4], lo[4];
#pragma unroll
    for (int c = 0; c < 4; c++) split2(hn[c], hi[c], lo[c]);
    __half* hp = g_hp + (long long)r * 3072 + e;
    *(__half2*)(hp)        = mkh2(hi[0], hi[1]); *(__half2*)(hp + 2)      = mkh2(hi[2], hi[3]);
    *(__half2*)(hp + 1024) = mkh2(lo[0], lo[1]); *(__half2*)(hp + 1026)   = mkh2(lo[2], lo[3]);
    *(__half2*)(hp + 2048) = mkh2(hi[0], hi[1]); *(__half2*)(hp + 2050)   = mkh2(hi[2], hi[3]);
}

__global__ void k_vnf(const float* __restrict__ vnow, const float* __restrict__ vall,
                      const float* __restrict__ Wn, const float* __restrict__ Wa)
{
    int b = blockIdx.x, d = threadIdx.x;
    float sn = 0.f, sa = 0.f;
#pragma unroll
    for (int k = 0; k < 16; k++) {
        sn = fmaf(vnow[b * 16 + k], Wn[k * 64 + d], sn);
        sa = fmaf(vall[b * 16 + k], Wa[k * 64 + d], sa);
    }
    g_vn[b * 64 + d] = sn;
    g_va[b * 64 + d] = sa;
}

// concat' = split([enc_out | npos | va | vn]) into g_cp [hi|lo|hi] pitch 3648
__global__ void k_concat(const int* __restrict__ from_node, const float* __restrict__ pos_enc)
{
    int r = blockIdx.x, b = r >> 8;
    __half* dst = g_cp + (long long)r * 3648;
    const float* hs = g_h + (long long)r * E_;
    {
        int i = threadIdx.x * 4;
        float4 v = *(const float4*)(hs + i);
        __half hi[4], lo[4];
        split2(v.x, hi[0], lo[0]); split2(v.y, hi[1], lo[1]);
        split2(v.z, hi[2], lo[2]); split2(v.w, hi[3], lo[3]);
        *(__half2*)(dst + i)            = mkh2(hi[0], hi[1]); *(__half2*)(dst + i + 2)        = mkh2(hi[2], hi[3]);
        *(__half2*)(dst + 1216 + i)     = mkh2(lo[0], lo[1]); *(__half2*)(dst + 1216 + i + 2) = mkh2(lo[2], lo[3]);
        *(__half2*)(dst + 2432 + i)     = mkh2(hi[0], hi[1]); *(__half2*)(dst + 2432 + i + 2) = mkh2(hi[2], hi[3]);
    }
    int fn = from_node[b];
    for (int i = threadIdx.x; i < 64; i += blockDim.x) {
        float v0 = pos_enc[fn * 64 + i], v1 = g_va[b * 64 + i], v2 = g_vn[b * 64 + i];
        __half hi, lo;
        split2(v0, hi, lo); dst[1024 + i] = hi; dst[2240 + i] = lo; dst[3456 + i] = hi;
        split2(v1, hi, lo); dst[1088 + i] = hi; dst[2304 + i] = lo; dst[3520 + i] = hi;
        split2(v2, hi, lo); dst[1152 + i] = hi; dst[2368 + i] = lo; dst[3584 + i] = hi;
    }
}

// decoder GRU (h0=0 => gh=bhh), 4 elems/thread
__global__ void k_decgru(const float* __restrict__ bhh, float* __restrict__ hidden_out)
{
    long long idx = ((long long)blockIdx.x * 256 + threadIdx.x) * 4;  // r*2048 + e
    int r = (int)(idx >> 11);
    int e = (int)(idx & 2047);
    const float* gi = g_gid + (long long)r * 6144 + e;
    float4 gir = *(const float4*)gi;
    float4 giz = *(const float4*)(gi + 2048);
    float4 gin = *(const float4*)(gi + 4096);
    float4 bhr = *(const float4*)(bhh + e);
    float4 bhz = *(const float4*)(bhh + 2048 + e);
    float4 bhn = *(const float4*)(bhh + 4096 + e);
    float hv[4];
    {
        const float* pir = &gir.x; const float* piz = &giz.x; const float* pin = &gin.x;
        const float* pbr = &bhr.x; const float* pbz = &bhz.x; const float* pbn = &bhn.x;
#pragma unroll
        for (int c = 0; c < 4; c++) {
            float rr = sigmoidf_(pir[c] + pbr[c]);
            float zz = sigmoidf_(piz[c] + pbz[c]);
            float nn = tanhf(pin[c] + rr * pbn[c]);
            hv[c] = (1.f - zz) * nn;
        }
    }
    float4 ho; ho.x = hv[0]; ho.y = hv[1]; ho.z = hv[2]; ho.w = hv[3];
    *(float4*)(hidden_out + idx) = ho;
    __half hi[4], lo[4];
#pragma unroll
    for (int c = 0; c < 4; c++) split2(hv[c], hi[c], lo[c]);
    __half* hp = g_hidp + (long long)r * 6144 + e;
    *(__half2*)(hp)        = mkh2(hi[0], hi[1]); *(__half2*)(hp + 2)      = mkh2(hi[2], hi[3]);
    *(__half2*)(hp + 2048) = mkh2(lo[0], lo[1]); *(__half2*)(hp + 2050)   = mkh2(lo[2], lo[3]);
    *(__half2*)(hp + 4096) = mkh2(hi[0], hi[1]); *(__half2*)(hp + 4098)   = mkh2(hi[2], hi[3]);
}

// thin head: out3 = mid @ W2^T + b2
__global__ void k_out2(const float* __restrict__ W2, const float* __restrict__ b2)
{
    __shared__ float w[3][1024];
    int tid = threadIdx.x;
    for (int i = tid; i < 3 * 1024; i += 256) w[i >> 10][i & 1023] = W2[i];
    __syncthreads();
    int warp = tid >> 5, lane = tid & 31;
    int r = blockIdx.x * 8 + warp;
    const float* m = g_mid + (long long)r * 1024;
    float s0 = 0.f, s1 = 0.f, s2 = 0.f;
    for (int k = lane; k < 1024; k += 32) {
        float mv = m[k];
        s0 = fmaf(mv, w[0][k], s0);
        s1 = fmaf(mv, w[1][k], s1);
        s2 = fmaf(mv, w[2][k], s2);
    }
#pragma unroll
    for (int off = 16; off; off >>= 1) {
        s0 += __shfl_down_sync(0xffffffffu, s0, off);
        s1 += __shfl_down_sync(0xffffffffu, s1, off);
        s2 += __shfl_down_sync(0xffffffffu, s2, off);
    }
    if (lane == 0) {
        g_out3[r * 3 + 0] = s0 + b2[0];
        g_out3[r * 3 + 1] = s1 + b2[1];
        g_out3[r * 3 + 2] = s2 + b2[2];
    }
}

__global__ void k_max()
{
    int b = blockIdx.x;
    __shared__ float sm[256];
    float mx = -INFINITY;
    for (int i = threadIdx.x; i < N_ * AACT_; i += 256)
        mx = fmaxf(mx, g_out3[b * N_ * AACT_ + i]);
    sm[threadIdx.x] = mx;
    __syncthreads();
    for (int s = 128; s; s >>= 1) {
        if (threadIdx.x < s) sm[threadIdx.x] = fmaxf(sm[threadIdx.x], sm[threadIdx.x + s]);
        __syncthreads();
    }
    if (threadIdx.x == 0) g_maxv[b] = sm[0];
}

__global__ void k_final(const int* __restrict__ mask, float* __restrict__ out)
{
    int r = blockIdx.x * 256 + threadIdx.x;
    if (r >= BN_) return;
    int b = r >> 8;
    float mv = g_maxv[b] + 1.f;
    float mf = (mask[r] == 1) ? 1.f : 1e10f;
    out[r]                 = mf * (g_out3[r * 3 + 0] - mv) + 1.f;
    out[BN_ + r * 2 + 0]   = mf * (g_out3[r * 3 + 1] - mv) + 1.f;
    out[BN_ + r * 2 + 1]   = mf * (g_out3[r * 3 + 2] - mv) + 1.f;
}

// ---------------- launcher ----------------------------------------------------
static GJob mkjob(const __half* A, const __half* Bm, int Kp,
                  long long sA, long long sB,
                  float* C, int ldc, const float* bias, int relu,
                  __half* spl, int splPitch, int splK, int colOff,
                  int gx, int gy, int batches)
{
    GJob j;
    j.A = A; j.B = Bm; j.Kp = Kp; j.sA = sA; j.sB = sB;
    j.C = C; j.ldc = ldc; j.bias = bias; j.relu = relu;
    j.spl = spl; j.splPitch = splPitch; j.splK = splK; j.colOff = colOff;
    j.gx = gx; j.gy = gy; j.nt = gx * gy * batches;
    return j;
}

extern "C" void kernel_launch(void* const* d_in, const int* in_sizes, int n_in,
                              void* d_out, int out_size)
{
    const float* annotation = (const float*)d_in[0];
    const float* A_out      = (const float*)d_in[1];
    const float* A_in       = (const float*)d_in[2];
    const int*   from_node  = (const int*)  d_in[3];
    const float* vnf_now    = (const float*)d_in[4];
    const float* vnf_all    = (const float*)d_in[5];
    const int*   mask       = (const int*)  d_in[6];
    const float* anno_W     = (const float*)d_in[7];
    const float* gru_Wih    = (const float*)d_in[8];
    const float* gru_Whh    = (const float*)d_in[9];
    const float* vnf_now_W  = (const float*)d_in[10];
    const float* vnf_all_W  = (const float*)d_in[11];
    const float* dgru_Wih   = (const float*)d_in[12];
    // d_in[13] = dgru_Whh: unused (h0 == 0 -> gh == dgru_bhh exactly)
    const float* dgru_bih   = (const float*)d_in[14];
    const float* dgru_bhh   = (const float*)d_in[15];
    const float* out_W1     = (const float*)d_in[16];
    const float* out_b1     = (const float*)d_in[17];
    const float* out_W2     = (const float*)d_in[18];
    const float* out_b2     = (const float*)d_in[19];
    const float* pos_enc    = (const float*)d_in[20];

    float* out = (float*)d_out;
    float* hidden = out + BN_ + BN_ * 2;

    cudaFuncSetAttribute(gemm_mma, cudaFuncAttributeMaxDynamicSharedMemorySize,
                         SMEM_TOTAL_GEMM);
    int nsm = 148;
    cudaDeviceGetAttribute(&nsm, cudaDevAttrMultiProcessorCount, 0);
    const int NPERS = nsm * 2;

    float *p_gi, *p_gh, *p_gid, *p_mid;
    __half *p_Wihp, *p_Whhp, *p_dWihp, *p_W1p, *p_adjO, *p_adjI;
    __half *p_ap, *p_hp, *p_ht, *p_cp, *p_hidp;
    cudaGetSymbolAddress((void**)&p_gi, g_gi);
    cudaGetSymbolAddress((void**)&p_gh, g_gh);
    cudaGetSymbolAddress((void**)&p_gid, g_gid);
    cudaGetSymbolAddress((void**)&p_mid, g_mid);
    cudaGetSymbolAddress((void**)&p_Wihp, g_Wihp);
    cudaGetSymbolAddress((void**)&p_Whhp, g_Whhp);
    cudaGetSymbolAddress((void**)&p_dWihp, g_dWihp);
    cudaGetSymbolAddress((void**)&p_W1p, g_W1p);
    cudaGetSymbolAddress((void**)&p_adjO, g_adjO);
    cudaGetSymbolAddress((void**)&p_adjI, g_adjI);
    cudaGetSymbolAddress((void**)&p_ap, g_ap);
    cudaGetSymbolAddress((void**)&p_hp, g_hp);
    cudaGetSymbolAddress((void**)&p_ht, g_ht);
    cudaGetSymbolAddress((void**)&p_cp, g_cp);
    cudaGetSymbolAddress((void**)&p_hidp, g_hidp);

    GJob jz; jz.nt = 0; jz.A = nullptr; jz.B = nullptr; jz.Kp = 64;
    jz.sA = 0; jz.sB = 0; jz.C = nullptr; jz.ldc = 0; jz.bias = nullptr;
    jz.relu = 0; jz.spl = nullptr; jz.splPitch = 0; jz.splK = 0; jz.colOff = 0;
    jz.gx = 1; jz.gy = 1;

    // ---- prep ----
    k_prepW<<<(3072 * 2048 + 255) / 256, 256>>>(gru_Wih, p_Wihp, 2048, 3072 * 2048);
    k_prepW<<<(3072 * 1024 + 255) / 256, 256>>>(gru_Whh, p_Whhp, 1024, 3072 * 1024);
    k_adjprep<<<(B_ * 256 * 256) / 256, 256>>>(A_out, A_in);
    k_embed<<<BN_, 256>>>(annotation, anno_W);

    // jobs (constant across steps)
    GJob jAdjO = mkjob(p_adjO, p_ht, 512, 256LL * 512, 1024LL * 512,
                       nullptr, 0, nullptr, 0, p_ap, 6144, 2048, 0, 8, 2, 32);
    GJob jAdjI = mkjob(p_adjI, p_ht, 512, 256LL * 512, 1024LL * 512,
                       nullptr, 0, nullptr, 0, p_ap, 6144, 2048, 1024, 8, 2, 32);
    GJob jGi   = mkjob(p_ap, p_Wihp, 6144, 0, 0, p_gi, 3072, nullptr, 0,
                       nullptr, 0, 0, 0, 24, 64, 1);
    GJob jGh   = mkjob(p_hp, p_Whhp, 3072, 0, 0, p_gh, 3072, nullptr, 0,
                       nullptr, 0, 0, 0, 24, 64, 1);

    // ---- T encoder GRU steps ----
    for (int t = 0; t < T_; t++) {
        k_transpose<<<dim3(32, 8, 32), dim3(32, 8)>>>();
        // merged adjacency (adjO + adjI), persistent
        gemm_mma<<<NPERS, 256, SMEM_TOTAL_GEMM>>>(jAdjO, jAdjI, jAdjO.nt + jAdjI.nt);
        // merged gi + gh, persistent
        gemm_mma<<<NPERS, 256, SMEM_TOTAL_GEMM>>>(jGi, jGh, jGi.nt + jGh.nt);
        k_gru<<<BN_ * E_ / 1024, 256>>>();
    }

    // ---- decoder prep + decoder ----
    k_prepW<<<(6144 * 1216 + 255) / 256, 256>>>(dgru_Wih, p_dWihp, 1216, 6144 * 1216);
    k_prepW<<<(1024 * 2048 + 255) / 256, 256>>>(out_W1, p_W1p, 2048, 1024 * 2048);
    k_vnf<<<B_, 64>>>(vnf_now, vnf_all, vnf_now_W, vnf_all_W);
    k_concat<<<BN_, 256>>>(from_node, pos_enc);
    // gi_dec = concat' @ dWih'^T + bih  [8192,6144] K'=3648
    GJob jDec = mkjob(p_cp, p_dWihp, 3648, 0, 0, p_gid, 6144, dgru_bih, 0,
                      nullptr, 0, 0, 0, 48, 64, 1);
    gemm_mma<<<NPERS, 256, SMEM_TOTAL_GEMM>>>(jDec, jz, jDec.nt);
    k_decgru<<<BN_ * 2 * E_ / 1024, 256>>>(dgru_bhh, hidden);
    // mid = relu(hidden' @ W1'^T + b1)  [8192,1024] K'=6144
    GJob jMid = mkjob(p_hidp, p_W1p, 6144, 0, 0, p_mid, 1024, out_b1, 1,
                      nullptr, 0, 0, 0, 8, 64, 1);
    gemm_mma<<<NPERS, 256, SMEM_TOTAL_GEMM>>>(jMid, jz, jMid.nt);

    // ---- head ----
    k_out2<<<BN_ / 8, 256>>>(out_W2, out_b2);
    k_max<<<B_, 256>>>();
    k_final<<<BN_ / 256, 256>>>(mask, out);
}